// round 1
// baseline (speedup 1.0000x reference)
#include <cuda_runtime.h>
#include <cstdint>
#include <cstddef>

#define L_ 8
#define M_ 128
#define K_ 32
#define D_ 16
#define B_ 2048
#define N_ 1024  /* L_*M_ */

// Scratch layout (element offsets into g_scratch):
//   [0, D_*B_)                : xT      (D, B)  transposed x
//   [TR_OFF, TR_OFF + N*D*B)  : traceT  (N, D, B) transposed trace
//   [OUT_OFF, OUT_OFF + N*D*B): outT    (N, D, B) transposed computed outputs
#define XT_OFF   0u
#define TR_OFF   ((unsigned)(D_ * B_))
#define OUT_OFF  ((unsigned)(D_ * B_ + N_ * D_ * B_))

static __device__ float g_scratch[(size_t)D_ * B_ + 2ull * N_ * D_ * B_];

// ---------------------------------------------------------------------------
// Transpose: per block, one (B, D) tile -> (D, B).  Block N_ handles x.
// Source rows are contiguous (full D=16 rows), so reads are pure float4
// streams; writes are contiguous per-d runs.  Smem tile padded to kill
// bank conflicts on the transposed read.
// ---------------------------------------------------------------------------
__global__ void __launch_bounds__(256) transpose_kernel(
    const float* __restrict__ trace, const float* __restrict__ x)
{
    __shared__ float tile[128 * 17];
    const int blk = blockIdx.x;
    const float* src = (blk < N_) ? (trace + (size_t)blk * B_ * D_) : x;
    float* dst = (blk < N_) ? (g_scratch + TR_OFF + (size_t)blk * D_ * B_)
                            : (g_scratch + XT_OFF);
    const int t = threadIdx.x;

    for (int ti = 0; ti < B_ / 128; ++ti) {
        const float4* s4 = reinterpret_cast<const float4*>(src + (size_t)ti * 128 * D_);
        #pragma unroll
        for (int j = t; j < 512; j += 256) {
            float4 v = s4[j];
            int bb = j >> 2;
            int dd = (j & 3) * 4;
            tile[bb * 17 + dd + 0] = v.x;
            tile[bb * 17 + dd + 1] = v.y;
            tile[bb * 17 + dd + 2] = v.z;
            tile[bb * 17 + dd + 3] = v.w;
        }
        __syncthreads();
        #pragma unroll
        for (int j = t; j < 2048; j += 256) {
            int d  = j >> 7;
            int bb = j & 127;
            dst[(size_t)d * B_ + ti * 128 + bb] = tile[bb * 17 + d];
        }
        __syncthreads();
    }
}

// ---------------------------------------------------------------------------
// Layer kernel: block = (node m, batch-tile), 256 threads, 2 batches/thread.
// Gathers are fully coalesced float2 loads from the transposed scratch.
// ---------------------------------------------------------------------------
__global__ void __launch_bounds__(256) layer_kernel(
    float* __restrict__ out,
    const int* __restrict__ src_node,
    const int* __restrict__ src_feat,
    const float* __restrict__ W,
    const float* __restrict__ bias,
    int l)
{
    const int m = blockIdx.x;
    const int n = l * M_ + m;
    const int t = threadIdx.x;
    const int tb = blockIdx.y * blockDim.x + t;  // batch-pair index, 0..1023
    const int b  = tb * 2;

    __shared__ float    sW[D_ * K_];
    __shared__ float    sBias[D_];
    __shared__ unsigned sOff[K_];

    sW[t]       = W[(size_t)n * (D_ * K_) + t];
    sW[t + 256] = W[(size_t)n * (D_ * K_) + t + 256];
    if (t < D_) sBias[t] = bias[n * D_ + t];
    if (t < K_) {
        int sn = src_node[n * K_ + t];
        int sf = src_feat[n * K_ + t];
        unsigned off;
        if (sn == 0) {
            off = XT_OFF + (unsigned)sf * B_;                       // cur[0] = x
        } else if (sn <= l * M_) {
            off = OUT_OFF + ((unsigned)(sn - 1) * D_ + (unsigned)sf) * B_;  // earlier layer output
        } else {
            off = TR_OFF  + ((unsigned)(sn - 1) * D_ + (unsigned)sf) * B_;  // stop-grad trace
        }
        sOff[t] = off;
    }
    __syncthreads();

    // Gather 32 source values for 2 batch elements each (coalesced LDG.64).
    float2 g[K_];
    #pragma unroll
    for (int k = 0; k < K_; ++k)
        g[k] = *reinterpret_cast<const float2*>(&g_scratch[sOff[k] + (unsigned)b]);

    float ax[D_], ay[D_];
    #pragma unroll
    for (int d = 0; d < D_; ++d) {
        float sx = sBias[d], sy = sx;
        #pragma unroll
        for (int k4 = 0; k4 < K_ / 4; ++k4) {
            float4 w = *reinterpret_cast<const float4*>(&sW[d * K_ + 4 * k4]);
            sx += w.x * g[4 * k4 + 0].x;  sy += w.x * g[4 * k4 + 0].y;
            sx += w.y * g[4 * k4 + 1].x;  sy += w.y * g[4 * k4 + 1].y;
            sx += w.z * g[4 * k4 + 2].x;  sy += w.z * g[4 * k4 + 2].y;
            sx += w.w * g[4 * k4 + 3].x;  sy += w.w * g[4 * k4 + 3].y;
        }
        ax[d] = fmaxf(sx, 0.0f);
        ay[d] = fmaxf(sy, 0.0f);
    }

    // Transposed copy for later-layer gathers (coalesced float2 per d).
    float* oT = g_scratch + OUT_OFF + (size_t)n * (D_ * B_);
    #pragma unroll
    for (int d = 0; d < D_; ++d)
        *reinterpret_cast<float2*>(&oT[d * B_ + b]) = make_float2(ax[d], ay[d]);

    // Final output (N, B, D): 2 batches x 64 B contiguous per thread.
    float* o = out + ((size_t)n * B_ + (size_t)b) * D_;
    #pragma unroll
    for (int d4 = 0; d4 < D_ / 4; ++d4) {
        *reinterpret_cast<float4*>(&o[4 * d4]) =
            make_float4(ax[4 * d4 + 0], ax[4 * d4 + 1], ax[4 * d4 + 2], ax[4 * d4 + 3]);
        *reinterpret_cast<float4*>(&o[D_ + 4 * d4]) =
            make_float4(ay[4 * d4 + 0], ay[4 * d4 + 1], ay[4 * d4 + 2], ay[4 * d4 + 3]);
    }
}

// ---------------------------------------------------------------------------
// Launch: one transpose, then 8 dependent layer kernels (same stream order
// gives the layer->layer dependency).  All graph-capturable, no allocs.
// ---------------------------------------------------------------------------
extern "C" void kernel_launch(void* const* d_in, const int* in_sizes, int n_in,
                              void* d_out, int out_size)
{
    const float* x      = (const float*)d_in[0];
    const float* trace  = (const float*)d_in[1];
    const int*   src_n  = (const int*)d_in[2];
    const int*   src_f  = (const int*)d_in[3];
    const float* W      = (const float*)d_in[4];
    const float* bias   = (const float*)d_in[5];
    float* out = (float*)d_out;

    transpose_kernel<<<N_ + 1, 256>>>(trace, x);
    for (int l = 0; l < L_; ++l)
        layer_kernel<<<dim3(M_, B_ / 512), 256>>>(out, src_n, src_f, W, bias, l);
}

// round 2
// speedup vs baseline: 1.2040x; 1.2040x over previous
#include <cuda_runtime.h>
#include <cstdint>
#include <cstddef>

#define L_ 8
#define M_ 128
#define K_ 32
#define D_ 16
#define B_ 2048
#define N_ 1024  /* L_*M_ */

// Scratch layout (element offsets into g_scratch):
//   [0, D_*B_)                : xT      (D, B)  transposed x
//   [TR_OFF, TR_OFF + N*D*B)  : traceT  (N, D, B) transposed trace
//   [OUT_OFF, OUT_OFF + N*D*B): outT    (N, D, B) transposed computed outputs
#define XT_OFF   0u
#define TR_OFF   ((unsigned)(D_ * B_))
#define OUT_OFF  ((unsigned)(D_ * B_ + N_ * D_ * B_))

static __device__ float g_scratch[(size_t)D_ * B_ + 2ull * N_ * D_ * B_];

// ---------------------------------------------------------------------------
// Transpose: per block, one (B, D) tile -> (D, B).  Block N_ handles x.
// ---------------------------------------------------------------------------
__global__ void __launch_bounds__(256) transpose_kernel(
    const float* __restrict__ trace, const float* __restrict__ x)
{
    __shared__ float tile[128 * 17];
    const int blk = blockIdx.x;
    const float* src = (blk < N_) ? (trace + (size_t)blk * B_ * D_) : x;
    float* dst = (blk < N_) ? (g_scratch + TR_OFF + (size_t)blk * D_ * B_)
                            : (g_scratch + XT_OFF);
    const int t = threadIdx.x;

    for (int ti = 0; ti < B_ / 128; ++ti) {
        const float4* s4 = reinterpret_cast<const float4*>(src + (size_t)ti * 128 * D_);
        #pragma unroll
        for (int j = t; j < 512; j += 256) {
            float4 v = s4[j];
            int bb = j >> 2;
            int dd = (j & 3) * 4;
            tile[bb * 17 + dd + 0] = v.x;
            tile[bb * 17 + dd + 1] = v.y;
            tile[bb * 17 + dd + 2] = v.z;
            tile[bb * 17 + dd + 3] = v.w;
        }
        __syncthreads();
        #pragma unroll
        for (int j = t; j < 2048; j += 256) {
            int d  = j >> 7;
            int bb = j & 127;
            dst[(size_t)d * B_ + ti * 128 + bb] = tile[bb * 17 + d];
        }
        __syncthreads();
    }
}

// ---------------------------------------------------------------------------
// Layer kernel: block = (node m, batch-tile of 256), 128 threads,
// 2 batches/thread.  Gathers streamed in chunks of 4 into persistent
// accumulators -> ~56 regs -> 8 blocks/SM (32 warps, occ ~50%).
// Grid (128, 8) = 1024 blocks = single wave on 148 SMs.
// ---------------------------------------------------------------------------
__global__ void __launch_bounds__(128, 8) layer_kernel(
    float* __restrict__ out,
    const int* __restrict__ src_node,
    const int* __restrict__ src_feat,
    const float* __restrict__ W,
    const float* __restrict__ bias,
    int l)
{
    const int m = blockIdx.x;
    const int n = l * M_ + m;
    const int t = threadIdx.x;
    const int b = (blockIdx.y * 128 + t) * 2;   // batch pair

    __shared__ float    sW[D_ * K_];
    __shared__ float    sBias[D_];
    __shared__ unsigned sOff[K_];

    #pragma unroll
    for (int i = t; i < D_ * K_; i += 128)
        sW[i] = W[(size_t)n * (D_ * K_) + i];
    if (t < D_) sBias[t] = bias[n * D_ + t];
    if (t < K_) {
        int sn = src_node[n * K_ + t];
        int sf = src_feat[n * K_ + t];
        unsigned off;
        if (sn == 0) {
            off = XT_OFF + (unsigned)sf * B_;                               // x
        } else if (sn <= l * M_) {
            off = OUT_OFF + ((unsigned)(sn - 1) * D_ + (unsigned)sf) * B_;  // earlier output
        } else {
            off = TR_OFF  + ((unsigned)(sn - 1) * D_ + (unsigned)sf) * B_;  // trace (stop-grad)
        }
        sOff[t] = off;
    }
    __syncthreads();

    float ax[D_], ay[D_];
    #pragma unroll
    for (int d = 0; d < D_; ++d) { ax[d] = sBias[d]; ay[d] = sBias[d]; }

    // Stream the 32 gathers in chunks of 4; FMA into 16x2 accumulators.
    #pragma unroll
    for (int kc = 0; kc < K_ / 4; ++kc) {
        float2 g0 = *reinterpret_cast<const float2*>(&g_scratch[sOff[4 * kc + 0] + (unsigned)b]);
        float2 g1 = *reinterpret_cast<const float2*>(&g_scratch[sOff[4 * kc + 1] + (unsigned)b]);
        float2 g2 = *reinterpret_cast<const float2*>(&g_scratch[sOff[4 * kc + 2] + (unsigned)b]);
        float2 g3 = *reinterpret_cast<const float2*>(&g_scratch[sOff[4 * kc + 3] + (unsigned)b]);
        #pragma unroll
        for (int d = 0; d < D_; ++d) {
            float4 w = *reinterpret_cast<const float4*>(&sW[d * K_ + 4 * kc]);
            ax[d] += w.x * g0.x + w.y * g1.x + w.z * g2.x + w.w * g3.x;
            ay[d] += w.x * g0.y + w.y * g1.y + w.z * g2.y + w.w * g3.y;
        }
    }

    #pragma unroll
    for (int d = 0; d < D_; ++d) {
        ax[d] = fmaxf(ax[d], 0.0f);
        ay[d] = fmaxf(ay[d], 0.0f);
    }

    // Transposed copy for later-layer gathers (coalesced float2 per d).
    float* oT = g_scratch + OUT_OFF + (size_t)n * (D_ * B_);
    #pragma unroll
    for (int d = 0; d < D_; ++d)
        *reinterpret_cast<float2*>(&oT[d * B_ + b]) = make_float2(ax[d], ay[d]);

    // Final output (N, B, D): 2 x 64 B contiguous per thread.
    float* o = out + ((size_t)n * B_ + (size_t)b) * D_;
    #pragma unroll
    for (int d4 = 0; d4 < D_ / 4; ++d4) {
        *reinterpret_cast<float4*>(&o[4 * d4]) =
            make_float4(ax[4 * d4 + 0], ax[4 * d4 + 1], ax[4 * d4 + 2], ax[4 * d4 + 3]);
        *reinterpret_cast<float4*>(&o[D_ + 4 * d4]) =
            make_float4(ay[4 * d4 + 0], ay[4 * d4 + 1], ay[4 * d4 + 2], ay[4 * d4 + 3]);
    }
}

extern "C" void kernel_launch(void* const* d_in, const int* in_sizes, int n_in,
                              void* d_out, int out_size)
{
    const float* x      = (const float*)d_in[0];
    const float* trace  = (const float*)d_in[1];
    const int*   src_n  = (const int*)d_in[2];
    const int*   src_f  = (const int*)d_in[3];
    const float* W      = (const float*)d_in[4];
    const float* bias   = (const float*)d_in[5];
    float* out = (float*)d_out;

    transpose_kernel<<<N_ + 1, 256>>>(trace, x);
    for (int l = 0; l < L_; ++l)
        layer_kernel<<<dim3(M_, B_ / 256), 128>>>(out, src_n, src_f, W, bias, l);
}

// round 3
// speedup vs baseline: 1.2762x; 1.0600x over previous
#include <cuda_runtime.h>
#include <cstdint>
#include <cstddef>

#define L_ 8
#define M_ 128
#define K_ 32
#define D_ 16
#define B_ 2048
#define N_ 1024  /* L_*M_ */

#define XT_OFF   0u
#define TR_OFF   ((unsigned)(D_ * B_))
#define OUT_OFF  ((unsigned)(D_ * B_ + N_ * D_ * B_))

static __device__ float g_scratch[(size_t)D_ * B_ + 2ull * N_ * D_ * B_];

// ---- packed fp32x2 helpers (sm_10x only) ----------------------------------
__device__ __forceinline__ unsigned long long fma2(
    unsigned long long a, unsigned long long b, unsigned long long c)
{
    unsigned long long d;
    asm("fma.rn.f32x2 %0, %1, %2, %3;" : "=l"(d) : "l"(a), "l"(b), "l"(c));
    return d;
}
__device__ __forceinline__ unsigned long long pack2(float lo, float hi)
{
    unsigned long long r;
    asm("mov.b64 %0, {%1, %2};" : "=l"(r) : "f"(lo), "f"(hi));
    return r;
}
__device__ __forceinline__ float2 unpack2(unsigned long long v)
{
    float2 r;
    asm("mov.b64 {%0, %1}, %2;" : "=f"(r.x), "=f"(r.y) : "l"(v));
    return r;
}

// ---------------------------------------------------------------------------
// Transpose: per block, one (B, D) tile -> (D, B).  Block N_ handles x.
// ---------------------------------------------------------------------------
__global__ void __launch_bounds__(256) transpose_kernel(
    const float* __restrict__ trace, const float* __restrict__ x)
{
    __shared__ float tile[128 * 17];
    const int blk = blockIdx.x;
    const float* src = (blk < N_) ? (trace + (size_t)blk * B_ * D_) : x;
    float* dst = (blk < N_) ? (g_scratch + TR_OFF + (size_t)blk * D_ * B_)
                            : (g_scratch + XT_OFF);
    const int t = threadIdx.x;

    for (int ti = 0; ti < B_ / 128; ++ti) {
        const float4* s4 = reinterpret_cast<const float4*>(src + (size_t)ti * 128 * D_);
        #pragma unroll
        for (int j = t; j < 512; j += 256) {
            float4 v = s4[j];
            int bb = j >> 2;
            int dd = (j & 3) * 4;
            tile[bb * 17 + dd + 0] = v.x;
            tile[bb * 17 + dd + 1] = v.y;
            tile[bb * 17 + dd + 2] = v.z;
            tile[bb * 17 + dd + 3] = v.w;
        }
        __syncthreads();
        #pragma unroll
        for (int j = t; j < 2048; j += 256) {
            int d  = j >> 7;
            int bb = j & 127;
            dst[(size_t)d * B_ + ti * 128 + bb] = tile[bb * 17 + d];
        }
        __syncthreads();
    }
}

// ---------------------------------------------------------------------------
// Layer kernel: block = (node m, batch-tile of 256), 128 threads,
// 2 batches/thread.  d-pair packed fp32x2 accumulation: weight pairs
// (W[d][k], W[d+1][k]) come pre-packed from transposed smem sWt[k][d].
// Gathers streamed in chunks of 8 for MLP.
// ---------------------------------------------------------------------------
__global__ void __launch_bounds__(128, 8) layer_kernel(
    float* __restrict__ out,
    const int* __restrict__ src_node,
    const int* __restrict__ src_feat,
    const float* __restrict__ W,
    const float* __restrict__ bias,
    int l)
{
    const int m = blockIdx.x;
    const int n = l * M_ + m;
    const int t = threadIdx.x;
    const int b = (blockIdx.y * 128 + t) * 2;   // batch pair

    __shared__ float    sWt[K_ * D_];   // sWt[k*16 + d] = W[n][d][k]
    __shared__ float    sBias[D_];
    __shared__ unsigned sOff[K_];

    #pragma unroll
    for (int i = t; i < D_ * K_; i += 128) {
        int d = i >> 5, k = i & 31;
        sWt[k * D_ + d] = W[(size_t)n * (D_ * K_) + i];
    }
    if (t < D_) sBias[t] = bias[n * D_ + t];
    if (t < K_) {
        int sn = src_node[n * K_ + t];
        int sf = src_feat[n * K_ + t];
        unsigned off;
        if (sn == 0) {
            off = XT_OFF + (unsigned)sf * B_;
        } else if (sn <= l * M_) {
            off = OUT_OFF + ((unsigned)(sn - 1) * D_ + (unsigned)sf) * B_;
        } else {
            off = TR_OFF  + ((unsigned)(sn - 1) * D_ + (unsigned)sf) * B_;
        }
        sOff[t] = off;
    }
    __syncthreads();

    // Accumulators: 8 d-pairs per batch, packed fp32x2.
    unsigned long long accx[D_ / 2], accy[D_ / 2];
    #pragma unroll
    for (int dp = 0; dp < D_ / 2; ++dp) {
        unsigned long long bp = pack2(sBias[2 * dp], sBias[2 * dp + 1]);
        accx[dp] = bp;
        accy[dp] = bp;
    }

    #pragma unroll
    for (int kc = 0; kc < K_ / 8; ++kc) {
        // 8 outstanding gathers (coalesced LDG.64 each).
        float2 g[8];
        #pragma unroll
        for (int j = 0; j < 8; ++j)
            g[j] = *reinterpret_cast<const float2*>(&g_scratch[sOff[8 * kc + j] + (unsigned)b]);

        #pragma unroll
        for (int j = 0; j < 8; ++j) {
            const int k = 8 * kc + j;
            unsigned long long gx = pack2(g[j].x, g[j].x);
            unsigned long long gy = pack2(g[j].y, g[j].y);
            const ulonglong2* wrow = reinterpret_cast<const ulonglong2*>(&sWt[k * D_]);
            #pragma unroll
            for (int q = 0; q < 4; ++q) {          // 4 x LDS.128 = 8 w-pairs
                ulonglong2 w2 = wrow[q];
                accx[2 * q + 0] = fma2(gx, w2.x, accx[2 * q + 0]);
                accx[2 * q + 1] = fma2(gx, w2.y, accx[2 * q + 1]);
                accy[2 * q + 0] = fma2(gy, w2.x, accy[2 * q + 0]);
                accy[2 * q + 1] = fma2(gy, w2.y, accy[2 * q + 1]);
            }
        }
    }

    float ax[D_], ay[D_];
    #pragma unroll
    for (int dp = 0; dp < D_ / 2; ++dp) {
        float2 vx = unpack2(accx[dp]), vy = unpack2(accy[dp]);
        ax[2 * dp]     = fmaxf(vx.x, 0.0f);
        ax[2 * dp + 1] = fmaxf(vx.y, 0.0f);
        ay[2 * dp]     = fmaxf(vy.x, 0.0f);
        ay[2 * dp + 1] = fmaxf(vy.y, 0.0f);
    }

    // Transposed copy for later-layer gathers (skip on last layer: never read).
    if (l != L_ - 1) {
        float* oT = g_scratch + OUT_OFF + (size_t)n * (D_ * B_);
        #pragma unroll
        for (int d = 0; d < D_; ++d)
            *reinterpret_cast<float2*>(&oT[d * B_ + b]) = make_float2(ax[d], ay[d]);
    }

    // Final output (N, B, D): 2 x 64 B contiguous per thread.
    float* o = out + ((size_t)n * B_ + (size_t)b) * D_;
    #pragma unroll
    for (int d4 = 0; d4 < D_ / 4; ++d4) {
        *reinterpret_cast<float4*>(&o[4 * d4]) =
            make_float4(ax[4 * d4 + 0], ax[4 * d4 + 1], ax[4 * d4 + 2], ax[4 * d4 + 3]);
        *reinterpret_cast<float4*>(&o[D_ + 4 * d4]) =
            make_float4(ay[4 * d4 + 0], ay[4 * d4 + 1], ay[4 * d4 + 2], ay[4 * d4 + 3]);
    }
}

extern "C" void kernel_launch(void* const* d_in, const int* in_sizes, int n_in,
                              void* d_out, int out_size)
{
    const float* x      = (const float*)d_in[0];
    const float* trace  = (const float*)d_in[1];
    const int*   src_n  = (const int*)d_in[2];
    const int*   src_f  = (const int*)d_in[3];
    const float* W      = (const float*)d_in[4];
    const float* bias   = (const float*)d_in[5];
    float* out = (float*)d_out;

    transpose_kernel<<<N_ + 1, 256>>>(trace, x);
    for (int l = 0; l < L_; ++l)
        layer_kernel<<<dim3(M_, B_ / 256), 128>>>(out, src_n, src_f, W, bias, l);
}